// round 5
// baseline (speedup 1.0000x reference)
#include <cuda_runtime.h>

#define HDIM 768
#define DDIM 16
#define MDIM 50
#define MPAD 64           // padded slot count (zero-filled) -> branch-free attention
#define NJ2  8            // DDIM/2 packed pairs
#define HC   12           // 768 / (32 lanes * 2 cols)
#define NWRP 8
#define NBLKA 592
#define NBLKB 592
#define MAXTOK 65536

typedef unsigned long long ull;

// ---------- packed f32x2 helpers ----------
__device__ __forceinline__ ull ffma2(ull a, ull b, ull c) {
    ull d;
    asm("fma.rn.f32x2 %0, %1, %2, %3;" : "=l"(d) : "l"(a), "l"(b), "l"(c));
    return d;
}
__device__ __forceinline__ ull add2(ull a, ull b) {
    ull d;
    asm("add.rn.f32x2 %0, %1, %2;" : "=l"(d) : "l"(a), "l"(b));
    return d;
}
__device__ __forceinline__ ull pack2(float lo, float hi) {
    ull r;
    asm("mov.b64 %0, {%1, %2};" : "=l"(r) : "f"(lo), "f"(hi));
    return r;
}
__device__ __forceinline__ ull packbb(float v) {
    ull r;
    asm("mov.b64 %0, {%1, %1};" : "=l"(r) : "f"(v));
    return r;
}
__device__ __forceinline__ void unpack2(ull v, float& lo, float& hi) {
    asm("mov.b64 {%0, %1}, %2;" : "=f"(lo), "=f"(hi) : "l"(v));
}

// ---------- device-global precomputed tensors / scratch ----------
__device__ __align__(16) ull g_W2d[NJ2 * HDIM];     // (g1*Wd)[i][2j2], [i][2j2+1]
__device__ __align__(16) ull g_W2u[NJ2 * HDIM];     // Wup[2j2][i], Wup[2j2+1][i]
__device__ __align__(16) ull g_key2[MPAD * NJ2];    // packed key pairs, zero-padded
__device__ __align__(16) ull g_val2[MPAD * NJ2];
__device__ float g_c1[DDIM];
__device__ float g_c2[DDIM];
__device__ __align__(16) ull g_memn[(size_t)MAXTOK * NJ2];   // LN3 output, packed pairs

__global__ void precompute_kernel(
    const float* __restrict__ g1, const float* __restrict__ b1,
    const float* __restrict__ Wd, const float* __restrict__ bd,
    const float* __restrict__ mem,
    const float* __restrict__ Wk, const float* __restrict__ bk,
    const float* __restrict__ Wv, const float* __restrict__ bv,
    const float* __restrict__ Wup)
{
    int gtid = blockIdx.x * blockDim.x + threadIdx.x;
    int gstr = gridDim.x * blockDim.x;

    for (int id = gtid; id < NJ2 * HDIM; id += gstr) {
        int j2 = id / HDIM, i = id % HDIM;
        float a = g1[i] * Wd[i * DDIM + 2 * j2];
        float b = g1[i] * Wd[i * DDIM + 2 * j2 + 1];
        g_W2d[id] = pack2(a, b);
        g_W2u[id] = pack2(Wup[(2 * j2) * HDIM + i], Wup[(2 * j2 + 1) * HDIM + i]);
    }
    // key / val packed pairs, padded slots zeroed
    for (int id = gtid; id < MPAD * NJ2; id += gstr) {
        int m = id / NJ2, j2 = id % NJ2;
        if (m < MDIM) {
            float ak0 = bk[2 * j2], ak1 = bk[2 * j2 + 1];
            float av0 = bv[2 * j2], av1 = bv[2 * j2 + 1];
            #pragma unroll
            for (int k = 0; k < DDIM; k++) {
                float mv = mem[m * DDIM + k];
                ak0 += mv * Wk[k * DDIM + 2 * j2];
                ak1 += mv * Wk[k * DDIM + 2 * j2 + 1];
                av0 += mv * Wv[k * DDIM + 2 * j2];
                av1 += mv * Wv[k * DDIM + 2 * j2 + 1];
            }
            g_key2[id] = pack2(ak0, ak1);
            g_val2[id] = pack2(av0, av1);
        } else {
            g_key2[id] = 0ull;
            g_val2[id] = 0ull;
        }
    }
    if (blockIdx.x < 2) {
        int warp = threadIdx.x >> 5, lane = threadIdx.x & 31;
        int j = blockIdx.x * 8 + warp;
        if (j < DDIM) {
            float c1 = 0.f, c2 = 0.f;
            for (int i = lane; i < HDIM; i += 32) {
                float w = Wd[i * DDIM + j];
                c1 += g1[i] * w;
                c2 += b1[i] * w;
            }
            #pragma unroll
            for (int off = 16; off > 0; off >>= 1) {
                c1 += __shfl_xor_sync(0xffffffffu, c1, off);
                c2 += __shfl_xor_sync(0xffffffffu, c2, off);
            }
            if (lane == 0) { g_c1[j] = c1; g_c2[j] = c2 + bd[j]; }
        }
    }
}

// =====================================================================
// Kernel A: LN1 + down-proj + LN2 + memory attention + LN3  -> g_memn
// 2 tokens per warp; middle computed per 16-lane segment.
// =====================================================================
__global__ __launch_bounds__(256, 4) void down_kernel(
    const float* __restrict__ x,
    const float* __restrict__ g2, const float* __restrict__ b2,
    const float* __restrict__ g3, const float* __restrict__ b3,
    int ntok)
{
    extern __shared__ ull sm[];
    ull* sW2d  = sm;                           // NJ2*HDIM
    ull* sKey2 = sW2d + NJ2 * HDIM;            // MPAD*NJ2
    ull* sVal2 = sKey2 + MPAD * NJ2;           // MPAD*NJ2
    float* sC1 = (float*)(sVal2 + MPAD * NJ2);
    float* sC2 = sC1 + DDIM;
    float* sG2 = sC2 + DDIM;
    float* sB2 = sG2 + DDIM;
    float* sG3 = sB2 + DDIM;
    float* sB3 = sG3 + DDIM;

    const int tid = threadIdx.x;
    for (int i = tid; i < NJ2 * HDIM; i += 256) sW2d[i] = g_W2d[i];
    for (int i = tid; i < MPAD * NJ2; i += 256) {
        sKey2[i] = g_key2[i];
        sVal2[i] = g_val2[i];
    }
    if (tid < DDIM) {
        sC1[tid] = g_c1[tid]; sC2[tid] = g_c2[tid];
        sG2[tid] = g2[tid];   sB2[tid] = b2[tid];
        sG3[tid] = g3[tid];   sB3[tid] = b3[tid];
    }
    __syncthreads();

    const int lane = tid & 31;
    const int warp = tid >> 5;
    const int gw = blockIdx.x * NWRP + warp;
    const int gstep = gridDim.x * NWRP * 2;
    const int sg = lane >> 4;        // segment (0/1) -> token within pair
    const int sl = lane & 15;        // lane within segment

    for (int tok0 = gw * 2; tok0 < ntok; tok0 += gstep) {
        int r1c = (tok0 + 1 < ntok) ? tok0 + 1 : ntok - 1;
        const float* xr0 = x + (size_t)tok0 * HDIM;
        const float* xr1 = x + (size_t)r1c * HDIM;

        // ---- pass 1: LN1 stats + packed down-proj dots
        ull t2a[NJ2], t2b[NJ2], s01a = 0ull, s01b = 0ull;
        #pragma unroll
        for (int j2 = 0; j2 < NJ2; j2++) { t2a[j2] = 0ull; t2b[j2] = 0ull; }

        #pragma unroll
        for (int c = 0; c < HC; c++) {
            const int i0 = c * 64 + lane * 2;
            float2 xv0 = *reinterpret_cast<const float2*>(xr0 + i0);
            float2 xv1 = *reinterpret_cast<const float2*>(xr1 + i0);
            ull p00 = packbb(xv0.x), p01 = packbb(xv0.y);
            ull p10 = packbb(xv1.x), p11 = packbb(xv1.y);
            s01a = ffma2(p00, pack2(1.f, xv0.x), s01a);
            s01a = ffma2(p01, pack2(1.f, xv0.y), s01a);
            s01b = ffma2(p10, pack2(1.f, xv1.x), s01b);
            s01b = ffma2(p11, pack2(1.f, xv1.y), s01b);
            #pragma unroll
            for (int j2 = 0; j2 < NJ2; j2++) {
                ulonglong2 w = *reinterpret_cast<const ulonglong2*>(sW2d + j2 * HDIM + i0);
                t2a[j2] = ffma2(p00, w.x, t2a[j2]);
                t2a[j2] = ffma2(p01, w.y, t2a[j2]);
                t2b[j2] = ffma2(p10, w.x, t2b[j2]);
                t2b[j2] = ffma2(p11, w.y, t2b[j2]);
            }
        }

        // ---- reduction: round 0 folds both tokens into 16-lane segments
        ull e[NJ2 + 1];
        {
            ull c0 = add2(s01a, __shfl_xor_sync(0xffffffffu, s01a, 16));
            ull c1 = add2(s01b, __shfl_xor_sync(0xffffffffu, s01b, 16));
            e[0] = (sg == 0) ? c0 : c1;
            #pragma unroll
            for (int j2 = 0; j2 < NJ2; j2++) {
                ull a = add2(t2a[j2], __shfl_xor_sync(0xffffffffu, t2a[j2], 16));
                ull b = add2(t2b[j2], __shfl_xor_sync(0xffffffffu, t2b[j2], 16));
                e[1 + j2] = (sg == 0) ? a : b;
            }
        }
        #pragma unroll
        for (int off = 8; off > 0; off >>= 1) {
            #pragma unroll
            for (int v = 0; v < NJ2 + 1; v++)
                e[v] = add2(e[v], __shfl_xor_sync(0xffffffffu, e[v], off));
        }

        // ---- middle (per segment; both tokens concurrently)
        const int tok = tok0 + sg;

        float s0, s1;
        unpack2(e[0], s0, s1);
        float mean = s0 * (1.f / HDIM);
        float var  = s1 * (1.f / HDIM) - mean * mean;
        float rstd = rsqrtf(var + 1e-12f);

        ull dva[NJ2];
        float dsum = 0.f;
        #pragma unroll
        for (int j2 = 0; j2 < NJ2; j2++) {
            float tl, th;
            unpack2(e[1 + j2], tl, th);
            float a = rstd * (tl - mean * sC1[2 * j2])     + sC2[2 * j2];
            float b = rstd * (th - mean * sC1[2 * j2 + 1]) + sC2[2 * j2 + 1];
            dva[j2] = pack2(a, b);
            dsum += a + b;
        }
        float dmean = dsum * (1.f / DDIM);
        float dvar = 0.f;
        #pragma unroll
        for (int j2 = 0; j2 < NJ2; j2++) {
            float a, b;
            unpack2(dva[j2], a, b);
            float fa = a - dmean, fb = b - dmean;
            dvar += fa * fa + fb * fb;
        }
        float drs = rsqrtf(dvar * (1.f / DDIM) + 1e-12f);

        ull qp[NJ2];
        #pragma unroll
        for (int j2 = 0; j2 < NJ2; j2++) {
            float a, b;
            unpack2(dva[j2], a, b);
            float qa = (a - dmean) * drs * sG2[2 * j2]     + sB2[2 * j2];
            float qb = (b - dmean) * drs * sG2[2 * j2 + 1] + sB2[2 * j2 + 1];
            qp[j2] = pack2(qa, qb);
        }

        // attention scores: lane sl handles slots sl, sl+16, sl+32, sl+48 (padded)
        float sc[4];
        #pragma unroll
        for (int k = 0; k < 4; k++) {
            int m = sl + 16 * k;
            ull acc = 0ull;
            #pragma unroll
            for (int j2 = 0; j2 < NJ2; j2++)
                acc = ffma2(qp[j2], sKey2[m * NJ2 + j2], acc);
            float l, h;
            unpack2(acc, l, h);
            sc[k] = l + h;
        }
        float mx = fmaxf(fmaxf(sc[0], sc[1]), fmaxf(sc[2], sc[3]));
        #pragma unroll
        for (int off = 8; off > 0; off >>= 1)
            mx = fmaxf(mx, __shfl_xor_sync(0xffffffffu, mx, off));

        float ex[4];
        #pragma unroll
        for (int k = 0; k < 4; k++) {
            int m = sl + 16 * k;
            ex[k] = (m < MDIM) ? __expf(sc[k] - mx) : 0.f;
        }

        // unnormalized mem_out (softmax 1/es cancels inside LN3)
        ull mo[NJ2];
        #pragma unroll
        for (int j2 = 0; j2 < NJ2; j2++) mo[j2] = 0ull;
        #pragma unroll
        for (int k = 0; k < 4; k++) {
            int m = sl + 16 * k;
            ull pb = packbb(ex[k]);
            #pragma unroll
            for (int j2 = 0; j2 < NJ2; j2++)
                mo[j2] = ffma2(pb, sVal2[m * NJ2 + j2], mo[j2]);
        }
        #pragma unroll
        for (int off = 8; off > 0; off >>= 1) {
            #pragma unroll
            for (int j2 = 0; j2 < NJ2; j2++)
                mo[j2] = add2(mo[j2], __shfl_xor_sync(0xffffffffu, mo[j2], off));
        }

        // LN3
        float msum = 0.f;
        #pragma unroll
        for (int j2 = 0; j2 < NJ2; j2++) {
            float l, h;
            unpack2(mo[j2], l, h);
            msum += l + h;
        }
        float mmean = msum * (1.f / DDIM);
        float mvar = 0.f;
        #pragma unroll
        for (int j2 = 0; j2 < NJ2; j2++) {
            float l, h;
            unpack2(mo[j2], l, h);
            float fl = l - mmean, fh = h - mmean;
            mvar += fl * fl + fh * fh;
        }
        float mrs = rsqrtf(mvar * (1.f / DDIM) + 1e-12f);

        ull qo[NJ2];
        #pragma unroll
        for (int j2 = 0; j2 < NJ2; j2++) {
            float l, h;
            unpack2(mo[j2], l, h);
            float oa = (l - mmean) * mrs * sG3[2 * j2]     + sB3[2 * j2];
            float ob = (h - mmean) * mrs * sG3[2 * j2 + 1] + sB3[2 * j2 + 1];
            qo[j2] = pack2(oa, ob);
        }

        if (sl == 0 && tok < ntok) {
            ull* dst = g_memn + (size_t)tok * NJ2;
            *reinterpret_cast<ulonglong2*>(dst)     = make_ulonglong2(qo[0], qo[1]);
            *reinterpret_cast<ulonglong2*>(dst + 2) = make_ulonglong2(qo[2], qo[3]);
            *reinterpret_cast<ulonglong2*>(dst + 4) = make_ulonglong2(qo[4], qo[5]);
            *reinterpret_cast<ulonglong2*>(dst + 6) = make_ulonglong2(qo[6], qo[7]);
        }
    }
}

// =====================================================================
// Kernel B: out = memn @ W_up + b_up   (2 tokens per warp)
// =====================================================================
__global__ __launch_bounds__(256, 4) void up_kernel(
    const float* __restrict__ bup, float* __restrict__ out, int ntok)
{
    extern __shared__ ull sm[];
    ull* sW2u = sm;                         // NJ2*HDIM
    float* sBup = (float*)(sW2u + NJ2 * HDIM);

    const int tid = threadIdx.x;
    for (int i = tid; i < NJ2 * HDIM; i += 256) sW2u[i] = g_W2u[i];
    for (int i = tid; i < HDIM; i += 256) sBup[i] = bup[i];
    __syncthreads();

    const int lane = tid & 31;
    const int warp = tid >> 5;
    const int gw = blockIdx.x * NWRP + warp;
    const int gstep = gridDim.x * NWRP * 2;

    for (int tok0 = gw * 2; tok0 < ntok; tok0 += gstep) {
        int r1c = (tok0 + 1 < ntok) ? tok0 + 1 : ntok - 1;
        bool st1 = (tok0 + 1 < ntok);

        ull q0[NJ2], q1[NJ2];
        {
            const ull* s0p = g_memn + (size_t)tok0 * NJ2;
            const ull* s1p = g_memn + (size_t)r1c * NJ2;
            #pragma unroll
            for (int k = 0; k < 4; k++) {
                ulonglong2 v0 = *reinterpret_cast<const ulonglong2*>(s0p + 2 * k);
                ulonglong2 v1 = *reinterpret_cast<const ulonglong2*>(s1p + 2 * k);
                q0[2 * k] = v0.x; q0[2 * k + 1] = v0.y;
                q1[2 * k] = v1.x; q1[2 * k + 1] = v1.y;
            }
        }

        float* or0 = out + (size_t)tok0 * HDIM;
        float* or1 = out + (size_t)r1c * HDIM;

        #pragma unroll
        for (int c = 0; c < HC; c++) {
            const int i0 = c * 64 + lane * 2;
            ull a00 = 0ull, a10 = 0ull, a01 = 0ull, a11 = 0ull;
            #pragma unroll
            for (int j2 = 0; j2 < NJ2; j2++) {
                ulonglong2 w = *reinterpret_cast<const ulonglong2*>(sW2u + j2 * HDIM + i0);
                a00 = ffma2(q0[j2], w.x, a00);
                a10 = ffma2(q0[j2], w.y, a10);
                a01 = ffma2(q1[j2], w.x, a01);
                a11 = ffma2(q1[j2], w.y, a11);
            }
            float bx = sBup[i0], by = sBup[i0 + 1];
            float l, h;
            float2 o0, o1;
            unpack2(a00, l, h); o0.x = l + h + bx;
            unpack2(a10, l, h); o0.y = l + h + by;
            unpack2(a01, l, h); o1.x = l + h + bx;
            unpack2(a11, l, h); o1.y = l + h + by;
            *reinterpret_cast<float2*>(or0 + i0) = o0;
            if (st1) *reinterpret_cast<float2*>(or1 + i0) = o1;
        }
    }
}

extern "C" void kernel_launch(void* const* d_in, const int* in_sizes, int n_in,
                              void* d_out, int out_size)
{
    const float* x   = (const float*)d_in[0];
    const float* g1  = (const float*)d_in[1];
    const float* b1  = (const float*)d_in[2];
    const float* Wd  = (const float*)d_in[3];
    const float* bd  = (const float*)d_in[4];
    const float* g2  = (const float*)d_in[5];
    const float* b2  = (const float*)d_in[6];
    const float* mem = (const float*)d_in[7];
    const float* Wk  = (const float*)d_in[8];
    const float* bk  = (const float*)d_in[9];
    const float* Wv  = (const float*)d_in[10];
    const float* bv  = (const float*)d_in[11];
    const float* g3  = (const float*)d_in[12];
    const float* b3  = (const float*)d_in[13];
    const float* Wup = (const float*)d_in[14];
    const float* bup = (const float*)d_in[15];
    float* out = (float*)d_out;

    int ntok = in_sizes[0] / HDIM;
    if (ntok > MAXTOK) ntok = MAXTOK;

    precompute_kernel<<<80, 256>>>(g1, b1, Wd, bd, mem, Wk, bk, Wv, bv, Wup);

    size_t smA = (size_t)(NJ2 * HDIM + 2 * MPAD * NJ2) * sizeof(ull)
               + (size_t)(6 * DDIM) * sizeof(float);
    size_t smB = (size_t)(NJ2 * HDIM) * sizeof(ull) + (size_t)HDIM * sizeof(float);

    cudaFuncSetAttribute(down_kernel, cudaFuncAttributeMaxDynamicSharedMemorySize, (int)smA);
    cudaFuncSetAttribute(up_kernel,   cudaFuncAttributeMaxDynamicSharedMemorySize, (int)smB);

    down_kernel<<<NBLKA, 256, smA>>>(x, g2, b2, g3, b3, ntok);
    up_kernel<<<NBLKB, 256, smB>>>(bup, out, ntok);
}

// round 6
// speedup vs baseline: 3.2750x; 3.2750x over previous
#include <cuda_runtime.h>

#define HDIM 768
#define DDIM 16
#define MDIM 50
#define MPAD 56           // padded slot count, 7 per lane of an 8-lane segment
#define KP   9            // key/val row pitch in ull (conflict-free: 72B stride)
#define NJ2  8            // DDIM/2 packed pairs
#define HC   12           // 768 / (32 lanes * 2 cols)
#define TTOK 4
#define NBLK 296
#define NWRP 8

typedef unsigned long long ull;

// ---------- packed f32x2 helpers ----------
__device__ __forceinline__ ull ffma2(ull a, ull b, ull c) {
    ull d;
    asm("fma.rn.f32x2 %0, %1, %2, %3;" : "=l"(d) : "l"(a), "l"(b), "l"(c));
    return d;
}
__device__ __forceinline__ ull add2(ull a, ull b) {
    ull d;
    asm("add.rn.f32x2 %0, %1, %2;" : "=l"(d) : "l"(a), "l"(b));
    return d;
}
__device__ __forceinline__ ull mul2(ull a, ull b) {
    ull d;
    asm("mul.rn.f32x2 %0, %1, %2;" : "=l"(d) : "l"(a), "l"(b));
    return d;
}
__device__ __forceinline__ ull pack2(float lo, float hi) {
    ull r;
    asm("mov.b64 %0, {%1, %2};" : "=l"(r) : "f"(lo), "f"(hi));
    return r;
}
__device__ __forceinline__ ull packbb(float v) {
    ull r;
    asm("mov.b64 %0, {%1, %1};" : "=l"(r) : "f"(v));
    return r;
}
__device__ __forceinline__ void unpack2(ull v, float& lo, float& hi) {
    asm("mov.b64 {%0, %1}, %2;" : "=f"(lo), "=f"(hi) : "l"(v));
}
__device__ __forceinline__ ull shfl64(ull v, int off) {
    return __shfl_xor_sync(0xffffffffu, v, off);
}

// ---------- precomputed tensors (device globals; zero-initialized) ----------
__device__ __align__(16) ull g_W2d[NJ2 * HDIM];     // (g1*Wd) packed j-pairs per H-col
__device__ __align__(16) ull g_W2u[NJ2 * HDIM];     // Wup packed j-pairs per H-col
__device__ __align__(16) ull g_key2[MPAD * KP];     // packed key pairs, pitch 9, zero-padded
__device__ __align__(16) ull g_val2[MPAD * KP];
__device__ float g_c1[DDIM];
__device__ float g_c2[DDIM];

__global__ void precompute_kernel(
    const float* __restrict__ g1, const float* __restrict__ b1,
    const float* __restrict__ Wd, const float* __restrict__ bd,
    const float* __restrict__ mem,
    const float* __restrict__ Wk, const float* __restrict__ bk,
    const float* __restrict__ Wv, const float* __restrict__ bv,
    const float* __restrict__ Wup)
{
    int gtid = blockIdx.x * blockDim.x + threadIdx.x;
    int gstr = gridDim.x * blockDim.x;

    for (int id = gtid; id < NJ2 * HDIM; id += gstr) {
        int j2 = id / HDIM, i = id % HDIM;
        float a = g1[i] * Wd[i * DDIM + 2 * j2];
        float b = g1[i] * Wd[i * DDIM + 2 * j2 + 1];
        g_W2d[id] = pack2(a, b);
        g_W2u[id] = pack2(Wup[(2 * j2) * HDIM + i], Wup[(2 * j2 + 1) * HDIM + i]);
    }
    for (int id = gtid; id < MDIM * NJ2; id += gstr) {
        int m = id / NJ2, j2 = id % NJ2;
        float ak0 = bk[2 * j2], ak1 = bk[2 * j2 + 1];
        float av0 = bv[2 * j2], av1 = bv[2 * j2 + 1];
        #pragma unroll
        for (int k = 0; k < DDIM; k++) {
            float mv = mem[m * DDIM + k];
            ak0 += mv * Wk[k * DDIM + 2 * j2];
            ak1 += mv * Wk[k * DDIM + 2 * j2 + 1];
            av0 += mv * Wv[k * DDIM + 2 * j2];
            av1 += mv * Wv[k * DDIM + 2 * j2 + 1];
        }
        g_key2[m * KP + j2] = pack2(ak0, ak1);
        g_val2[m * KP + j2] = pack2(av0, av1);
    }
    if (blockIdx.x < 2) {
        int warp = threadIdx.x >> 5, lane = threadIdx.x & 31;
        int j = blockIdx.x * 8 + warp;
        if (j < DDIM) {
            float c1 = 0.f, c2 = 0.f;
            for (int i = lane; i < HDIM; i += 32) {
                float w = Wd[i * DDIM + j];
                c1 += g1[i] * w;
                c2 += b1[i] * w;
            }
            #pragma unroll
            for (int off = 16; off > 0; off >>= 1) {
                c1 += __shfl_xor_sync(0xffffffffu, c1, off);
                c2 += __shfl_xor_sync(0xffffffffu, c2, off);
            }
            if (lane == 0) { g_c1[j] = c1; g_c2[j] = c2 + bd[j]; }
        }
    }
}

__global__ __launch_bounds__(256, 2) void fused_kernel(
    const float* __restrict__ x,
    const float* __restrict__ bup,
    const float* __restrict__ g2, const float* __restrict__ b2,
    const float* __restrict__ g3, const float* __restrict__ b3,
    float* __restrict__ out, int ntok)
{
    extern __shared__ ull sm[];
    ull* sW2d  = sm;                              // 6144
    ull* sW2u  = sW2d + NJ2 * HDIM;               // 6144
    ull* sKey2 = sW2u + NJ2 * HDIM;               // 504
    ull* sVal2 = sKey2 + MPAD * KP;               // 504
    ull* sXch  = sVal2 + MPAD * KP;               // NWRP*32 = 256
    float* sC1 = (float*)(sXch + NWRP * 32);
    float* sC2 = sC1 + DDIM;
    float* sG2 = sC2 + DDIM;
    float* sB2 = sG2 + DDIM;
    float* sG3 = sB2 + DDIM;
    float* sB3 = sG3 + DDIM;

    const int tid = threadIdx.x;
    for (int i = tid; i < NJ2 * HDIM; i += 256) {
        sW2d[i] = g_W2d[i];
        sW2u[i] = g_W2u[i];
    }
    for (int i = tid; i < MPAD * KP; i += 256) {
        sKey2[i] = g_key2[i];
        sVal2[i] = g_val2[i];
    }
    if (tid < DDIM) {
        sC1[tid] = g_c1[tid]; sC2[tid] = g_c2[tid];
        sG2[tid] = g2[tid];   sB2[tid] = b2[tid];
        sG3[tid] = g3[tid];   sB3[tid] = b3[tid];
    }
    __syncthreads();

    const int lane = tid & 31;
    const int warp = tid >> 5;
    const int sg = lane >> 4;          // bit4: half
    const int qb = (lane >> 3) & 1;    // bit3: quarter
    const int tt = lane >> 3;          // token owned by this 8-lane segment (0..3)
    const int sl7 = lane & 7;          // lane within segment
    const int gw = blockIdx.x * NWRP + warp;
    const int gstride = NBLK * NWRP * TTOK;

    for (int tok0 = gw * TTOK; tok0 < ntok; tok0 += gstride) {
        int row[TTOK];
        #pragma unroll
        for (int t = 0; t < TTOK; t++) {
            int r = tok0 + t;
            row[t] = (r < ntok) ? r : (ntok - 1);
        }
        const float* xr0 = x + (size_t)row[0] * HDIM;
        const float* xr1 = x + (size_t)row[1] * HDIM;
        const float* xr2 = x + (size_t)row[2] * HDIM;
        const float* xr3 = x + (size_t)row[3] * HDIM;

        // ---------------- pass 1: LN1 stats + packed down-projection ----------------
        ull t2[TTOK][NJ2];
        float s0[TTOK], s1[TTOK];
        #pragma unroll
        for (int t = 0; t < TTOK; t++) {
            s0[t] = 0.f; s1[t] = 0.f;
            #pragma unroll
            for (int j2 = 0; j2 < NJ2; j2++) t2[t][j2] = 0ull;
        }

        #pragma unroll
        for (int c = 0; c < HC; c++) {
            const int i0 = c * 64 + lane * 2;
            float2 xv0 = *reinterpret_cast<const float2*>(xr0 + i0);
            float2 xv1 = *reinterpret_cast<const float2*>(xr1 + i0);
            float2 xv2 = *reinterpret_cast<const float2*>(xr2 + i0);
            float2 xv3 = *reinterpret_cast<const float2*>(xr3 + i0);

            s0[0] += xv0.x + xv0.y;  s1[0] += xv0.x * xv0.x + xv0.y * xv0.y;
            s0[1] += xv1.x + xv1.y;  s1[1] += xv1.x * xv1.x + xv1.y * xv1.y;
            s0[2] += xv2.x + xv2.y;  s1[2] += xv2.x * xv2.x + xv2.y * xv2.y;
            s0[3] += xv3.x + xv3.y;  s1[3] += xv3.x * xv3.x + xv3.y * xv3.y;

            ull xp[TTOK][2];
            xp[0][0] = packbb(xv0.x); xp[0][1] = packbb(xv0.y);
            xp[1][0] = packbb(xv1.x); xp[1][1] = packbb(xv1.y);
            xp[2][0] = packbb(xv2.x); xp[2][1] = packbb(xv2.y);
            xp[3][0] = packbb(xv3.x); xp[3][1] = packbb(xv3.y);

            #pragma unroll
            for (int j2 = 0; j2 < NJ2; j2++) {
                ulonglong2 w = *reinterpret_cast<const ulonglong2*>(sW2d + j2 * HDIM + i0);
                #pragma unroll
                for (int t = 0; t < TTOK; t++) {
                    t2[t][j2] = ffma2(xp[t][0], w.x, t2[t][j2]);
                    t2[t][j2] = ffma2(xp[t][1], w.y, t2[t][j2]);
                }
            }
        }

        // ---------------- fold reduction: token t -> 8-lane group t ----------------
        // Round A (off16) + select by bit4; Round B (off8) + select by bit3;
        // then 3 butterfly rounds within the 8-lane group. All values packed f32x2.
        ull E[NJ2 + 1];
        #pragma unroll
        for (int v = 0; v < NJ2 + 1; v++) {
            ull v0 = (v == 0) ? pack2(s0[0], s1[0]) : t2[0][v - 1];
            ull v1 = (v == 0) ? pack2(s0[1], s1[1]) : t2[1][v - 1];
            ull v2 = (v == 0) ? pack2(s0[2], s1[2]) : t2[2][v - 1];
            ull v3 = (v == 0) ? pack2(s0[3], s1[3]) : t2[3][v - 1];
            ull w0 = add2(v0, shfl64(v0, 16));
            ull w1 = add2(v1, shfl64(v1, 16));
            ull w2 = add2(v2, shfl64(v2, 16));
            ull w3 = add2(v3, shfl64(v3, 16));
            ull ea = sg ? w2 : w0;
            ull eb = sg ? w3 : w1;
            ull ya = add2(ea, shfl64(ea, 8));
            ull yb = add2(eb, shfl64(eb, 8));
            ull e = qb ? yb : ya;
            e = add2(e, shfl64(e, 4));
            e = add2(e, shfl64(e, 2));
            e = add2(e, shfl64(e, 1));
            E[v] = e;
        }

        // ---------------- middle (per 8-lane segment; 4 tokens in parallel) ---------
        float s0v, s1v;
        unpack2(E[0], s0v, s1v);
        float mean = s0v * (1.f / HDIM);
        float var  = s1v * (1.f / HDIM) - mean * mean;
        float rstd = rsqrtf(var + 1e-12f);

        float dv[DDIM];
        float dsum = 0.f;
        #pragma unroll
        for (int j2 = 0; j2 < NJ2; j2++) {
            float tl, th;
            unpack2(E[1 + j2], tl, th);
            float a = rstd * (tl - mean * sC1[2 * j2])     + sC2[2 * j2];
            float b = rstd * (th - mean * sC1[2 * j2 + 1]) + sC2[2 * j2 + 1];
            dv[2 * j2] = a; dv[2 * j2 + 1] = b;
            dsum += a + b;
        }
        float dmean = dsum * (1.f / DDIM);
        float dvar = 0.f;
        #pragma unroll
        for (int j = 0; j < DDIM; j++) { float df = dv[j] - dmean; dvar += df * df; }
        float drs = rsqrtf(dvar * (1.f / DDIM) + 1e-12f);

        ull qp[NJ2];
        #pragma unroll
        for (int j2 = 0; j2 < NJ2; j2++) {
            float qa = (dv[2 * j2]     - dmean) * drs * sG2[2 * j2]     + sB2[2 * j2];
            float qc = (dv[2 * j2 + 1] - dmean) * drs * sG2[2 * j2 + 1] + sB2[2 * j2 + 1];
            qp[j2] = pack2(qa, qc);
        }

        // attention: lane sl7 owns slots sl7+8k, k=0..6 (padded to 56)
        float sc[7];
        #pragma unroll
        for (int k = 0; k < 7; k++) {
            const ull* kr = sKey2 + (sl7 + 8 * k) * KP;
            ull acc = 0ull;
            #pragma unroll
            for (int j2 = 0; j2 < NJ2; j2++) acc = ffma2(qp[j2], kr[j2], acc);
            float l, h;
            unpack2(acc, l, h);
            sc[k] = l + h;
        }
        float mx = sc[0];
        #pragma unroll
        for (int k = 1; k < 7; k++) mx = fmaxf(mx, sc[k]);
        #pragma unroll
        for (int off = 4; off > 0; off >>= 1)
            mx = fmaxf(mx, __shfl_xor_sync(0xffffffffu, mx, off));

        float ex[7];
        #pragma unroll
        for (int k = 0; k < 6; k++) ex[k] = __expf(sc[k] - mx);
        ex[6] = (sl7 < 2) ? __expf(sc[6] - mx) : 0.f;   // slots 48..49 real, 50..55 pad

        float es = ex[0] + ex[1] + ex[2] + ex[3] + ex[4] + ex[5] + ex[6];
        #pragma unroll
        for (int off = 4; off > 0; off >>= 1)
            es += __shfl_xor_sync(0xffffffffu, es, off);
        float inv = 1.f / es;

        ull mo[NJ2];
        #pragma unroll
        for (int j2 = 0; j2 < NJ2; j2++) mo[j2] = 0ull;
        #pragma unroll
        for (int k = 0; k < 7; k++) {
            const ull* vr = sVal2 + (sl7 + 8 * k) * KP;
            ull pb = packbb(ex[k]);
            #pragma unroll
            for (int j2 = 0; j2 < NJ2; j2++) mo[j2] = ffma2(pb, vr[j2], mo[j2]);
        }
        #pragma unroll
        for (int off = 4; off > 0; off >>= 1) {
            #pragma unroll
            for (int j2 = 0; j2 < NJ2; j2++)
                mo[j2] = add2(mo[j2], shfl64(mo[j2], off));
        }
        ull pinv = packbb(inv);
        #pragma unroll
        for (int j2 = 0; j2 < NJ2; j2++) mo[j2] = mul2(mo[j2], pinv);

        // LN3
        float msum = 0.f;
        #pragma unroll
        for (int j2 = 0; j2 < NJ2; j2++) {
            float l, h;
            unpack2(mo[j2], l, h);
            msum += l + h;
        }
        float mmean = msum * (1.f / DDIM);
        float mvar = 0.f;
        #pragma unroll
        for (int j2 = 0; j2 < NJ2; j2++) {
            float l, h;
            unpack2(mo[j2], l, h);
            float fl = l - mmean, fh = h - mmean;
            mvar += fl * fl + fh * fh;
        }
        float mrs = rsqrtf(mvar * (1.f / DDIM) + 1e-12f);

        ull qo[NJ2];
        #pragma unroll
        for (int j2 = 0; j2 < NJ2; j2++) {
            float l, h;
            unpack2(mo[j2], l, h);
            float oa = (l - mmean) * mrs * sG3[2 * j2]     + sB3[2 * j2];
            float ob = (h - mmean) * mrs * sG3[2 * j2 + 1] + sB3[2 * j2 + 1];
            qo[j2] = pack2(oa, ob);
        }

        // ---------------- exchange qo across the warp via smem ----------------
        ull* xch = sXch + warp * 32;
        __syncwarp();
        if (sl7 == 0) {
            ull* dst = xch + tt * 8;
            *reinterpret_cast<ulonglong2*>(dst)     = make_ulonglong2(qo[0], qo[1]);
            *reinterpret_cast<ulonglong2*>(dst + 2) = make_ulonglong2(qo[2], qo[3]);
            *reinterpret_cast<ulonglong2*>(dst + 4) = make_ulonglong2(qo[4], qo[5]);
            *reinterpret_cast<ulonglong2*>(dst + 6) = make_ulonglong2(qo[6], qo[7]);
        }
        __syncwarp();
        ull q2[TTOK][NJ2];
        #pragma unroll
        for (int t = 0; t < TTOK; t++) {
            #pragma unroll
            for (int k = 0; k < 4; k++) {
                ulonglong2 v = *reinterpret_cast<const ulonglong2*>(xch + t * 8 + 2 * k);
                q2[t][2 * k] = v.x;
                q2[t][2 * k + 1] = v.y;
            }
        }

        // ---------------- up-projection: out = memn @ W_up + b_up ----------------
        bool st[TTOK];
        #pragma unroll
        for (int t = 0; t < TTOK; t++) st[t] = (tok0 + t) < ntok;
        float* or0 = out + (size_t)row[0] * HDIM;
        float* or1 = out + (size_t)row[1] * HDIM;
        float* or2 = out + (size_t)row[2] * HDIM;
        float* or3 = out + (size_t)row[3] * HDIM;

        #pragma unroll
        for (int c = 0; c < HC; c++) {
            const int i0 = c * 64 + lane * 2;
            ull a0[TTOK], a1[TTOK];
            #pragma unroll
            for (int t = 0; t < TTOK; t++) { a0[t] = 0ull; a1[t] = 0ull; }

            #pragma unroll
            for (int j2 = 0; j2 < NJ2; j2++) {
                ulonglong2 w = *reinterpret_cast<const ulonglong2*>(sW2u + j2 * HDIM + i0);
                #pragma unroll
                for (int t = 0; t < TTOK; t++) {
                    a0[t] = ffma2(q2[t][j2], w.x, a0[t]);
                    a1[t] = ffma2(q2[t][j2], w.y, a1[t]);
                }
            }
            float2 bv2 = __ldg(reinterpret_cast<const float2*>(bup + i0));
            #pragma unroll
            for (int t = 0; t < TTOK; t++) {
                float l0, h0, l1, h1v;
                unpack2(a0[t], l0, h0);
                unpack2(a1[t], l1, h1v);
                float2 o;
                o.x = l0 + h0 + bv2.x;
                o.y = l1 + h1v + bv2.y;
                if (st[t]) {
                    float* orow = (t == 0) ? or0 : (t == 1) ? or1 : (t == 2) ? or2 : or3;
                    *reinterpret_cast<float2*>(orow + i0) = o;
                }
            }
        }
    }
}

extern "C" void kernel_launch(void* const* d_in, const int* in_sizes, int n_in,
                              void* d_out, int out_size)
{
    const float* x   = (const float*)d_in[0];
    const float* g1  = (const float*)d_in[1];
    const float* b1  = (const float*)d_in[2];
    const float* Wd  = (const float*)d_in[3];
    const float* bd  = (const float*)d_in[4];
    const float* g2  = (const float*)d_in[5];
    const float* b2  = (const float*)d_in[6];
    const float* mem = (const float*)d_in[7];
    const float* Wk  = (const float*)d_in[8];
    const float* bk  = (const float*)d_in[9];
    const float* Wv  = (const float*)d_in[10];
    const float* bv  = (const float*)d_in[11];
    const float* g3  = (const float*)d_in[12];
    const float* b3  = (const float*)d_in[13];
    const float* Wup = (const float*)d_in[14];
    const float* bup = (const float*)d_in[15];
    float* out = (float*)d_out;

    int ntok = in_sizes[0] / HDIM;

    precompute_kernel<<<64, 256>>>(g1, b1, Wd, bd, mem, Wk, bk, Wv, bv, Wup);

    size_t smembytes = (size_t)(2 * NJ2 * HDIM + 2 * MPAD * KP + NWRP * 32) * sizeof(ull)
                     + (size_t)(6 * DDIM) * sizeof(float);
    cudaFuncSetAttribute(fused_kernel, cudaFuncAttributeMaxDynamicSharedMemorySize, (int)smembytes);
    fused_kernel<<<NBLK, 256, smembytes>>>(x, bup, g2, b2, g3, b3, out, ntok);
}

// round 7
// speedup vs baseline: 3.3296x; 1.0167x over previous
#include <cuda_runtime.h>

#define HDIM 768
#define DDIM 16
#define MDIM 50
#define MPAD 56           // padded slot count, 7 per lane of an 8-lane segment
#define KP   9            // key/val row pitch in ull (conflict-free)
#define NJ2  8            // DDIM/2 packed pairs
#define HC   12           // 768 / (32 lanes * 2 cols)
#define TTOK 4
#define NBLK 296
#define NWRP 8
#define TB   128          // tokens per tile in up kernel

typedef unsigned long long ull;

// ---------- packed f32x2 helpers ----------
__device__ __forceinline__ ull ffma2(ull a, ull b, ull c) {
    ull d;
    asm("fma.rn.f32x2 %0, %1, %2, %3;" : "=l"(d) : "l"(a), "l"(b), "l"(c));
    return d;
}
__device__ __forceinline__ ull add2(ull a, ull b) {
    ull d;
    asm("add.rn.f32x2 %0, %1, %2;" : "=l"(d) : "l"(a), "l"(b));
    return d;
}
__device__ __forceinline__ ull pack2(float lo, float hi) {
    ull r;
    asm("mov.b64 %0, {%1, %2};" : "=l"(r) : "f"(lo), "f"(hi));
    return r;
}
__device__ __forceinline__ ull packbb(float v) {
    ull r;
    asm("mov.b64 %0, {%1, %1};" : "=l"(r) : "f"(v));
    return r;
}
__device__ __forceinline__ void unpack2(ull v, float& lo, float& hi) {
    asm("mov.b64 {%0, %1}, %2;" : "=f"(lo), "=f"(hi) : "l"(v));
}
__device__ __forceinline__ ull shfl64(ull v, int off) {
    return __shfl_xor_sync(0xffffffffu, v, off);
}

// ---------- device-global precomputed tensors / scratch ----------
__device__ __align__(16) ull g_W2d[NJ2 * HDIM];
__device__ __align__(16) ull g_key2[MPAD * KP];
__device__ __align__(16) ull g_val2[MPAD * KP];
__device__ float g_c1[DDIM];
__device__ float g_c2[DDIM];
__device__ __align__(16) ull g_memn[(size_t)65536 * NJ2];   // LN3 output, packed pairs

__global__ void precompute_kernel(
    const float* __restrict__ g1, const float* __restrict__ b1,
    const float* __restrict__ Wd, const float* __restrict__ bd,
    const float* __restrict__ mem,
    const float* __restrict__ Wk, const float* __restrict__ bk,
    const float* __restrict__ Wv, const float* __restrict__ bv)
{
    int gtid = blockIdx.x * blockDim.x + threadIdx.x;
    int gstr = gridDim.x * blockDim.x;

    for (int id = gtid; id < NJ2 * HDIM; id += gstr) {
        int j2 = id / HDIM, i = id % HDIM;
        float a = g1[i] * Wd[i * DDIM + 2 * j2];
        float b = g1[i] * Wd[i * DDIM + 2 * j2 + 1];
        g_W2d[id] = pack2(a, b);
    }
    for (int id = gtid; id < MDIM * NJ2; id += gstr) {
        int m = id / NJ2, j2 = id % NJ2;
        float ak0 = bk[2 * j2], ak1 = bk[2 * j2 + 1];
        float av0 = bv[2 * j2], av1 = bv[2 * j2 + 1];
        #pragma unroll
        for (int k = 0; k < DDIM; k++) {
            float mv = mem[m * DDIM + k];
            ak0 += mv * Wk[k * DDIM + 2 * j2];
            ak1 += mv * Wk[k * DDIM + 2 * j2 + 1];
            av0 += mv * Wv[k * DDIM + 2 * j2];
            av1 += mv * Wv[k * DDIM + 2 * j2 + 1];
        }
        g_key2[m * KP + j2] = pack2(ak0, ak1);
        g_val2[m * KP + j2] = pack2(av0, av1);
    }
    if (blockIdx.x < 2) {
        int warp = threadIdx.x >> 5, lane = threadIdx.x & 31;
        int j = blockIdx.x * 8 + warp;
        if (j < DDIM) {
            float c1 = 0.f, c2 = 0.f;
            #pragma unroll   // fully unroll: 24 independent load pairs, no serial chain
            for (int it = 0; it < HDIM / 32; it++) {
                int i = it * 32 + lane;
                float w = Wd[i * DDIM + j];
                c1 += g1[i] * w;
                c2 += b1[i] * w;
            }
            #pragma unroll
            for (int off = 16; off > 0; off >>= 1) {
                c1 += __shfl_xor_sync(0xffffffffu, c1, off);
                c2 += __shfl_xor_sync(0xffffffffu, c2, off);
            }
            if (lane == 0) { g_c1[j] = c1; g_c2[j] = c2 + bd[j]; }
        }
    }
}

// =====================================================================
// Kernel A: LN1 + down-proj + LN2 + attention + LN3 -> g_memn (packed)
// =====================================================================
__global__ __launch_bounds__(256, 2) void down_kernel(
    const float* __restrict__ x,
    const float* __restrict__ g2, const float* __restrict__ b2,
    const float* __restrict__ g3, const float* __restrict__ b3,
    int ntok)
{
    extern __shared__ ull sm[];
    ull* sW2d  = sm;                              // 6144
    ull* sKey2 = sW2d + NJ2 * HDIM;               // 504
    ull* sVal2 = sKey2 + MPAD * KP;               // 504
    float* sC1 = (float*)(sVal2 + MPAD * KP);
    float* sC2 = sC1 + DDIM;
    float* sG2 = sC2 + DDIM;
    float* sB2 = sG2 + DDIM;
    float* sG3 = sB2 + DDIM;
    float* sB3 = sG3 + DDIM;

    const int tid = threadIdx.x;
    for (int i = tid; i < NJ2 * HDIM; i += 256) sW2d[i] = g_W2d[i];
    for (int i = tid; i < MPAD * KP; i += 256) {
        sKey2[i] = g_key2[i];
        sVal2[i] = g_val2[i];
    }
    if (tid < DDIM) {
        sC1[tid] = g_c1[tid]; sC2[tid] = g_c2[tid];
        sG2[tid] = g2[tid];   sB2[tid] = b2[tid];
        sG3[tid] = g3[tid];   sB3[tid] = b3[tid];
    }
    __syncthreads();

    const int lane = tid & 31;
    const int warp = tid >> 5;
    const int sg = lane >> 4;
    const int qb = (lane >> 3) & 1;
    const int tt = lane >> 3;          // token index within group owned by segment
    const int sl7 = lane & 7;
    const int gw = blockIdx.x * NWRP + warp;
    const int gstride = NBLK * NWRP * TTOK;

    for (int tok0 = gw * TTOK; tok0 < ntok; tok0 += gstride) {
        int row[TTOK];
        #pragma unroll
        for (int t = 0; t < TTOK; t++) {
            int r = tok0 + t;
            row[t] = (r < ntok) ? r : (ntok - 1);
        }
        const float* xr0 = x + (size_t)row[0] * HDIM;
        const float* xr1 = x + (size_t)row[1] * HDIM;
        const float* xr2 = x + (size_t)row[2] * HDIM;
        const float* xr3 = x + (size_t)row[3] * HDIM;

        // ---- pass 1: LN1 stats + packed down-projection
        ull t2[TTOK][NJ2];
        float s0[TTOK], s1[TTOK];
        #pragma unroll
        for (int t = 0; t < TTOK; t++) {
            s0[t] = 0.f; s1[t] = 0.f;
            #pragma unroll
            for (int j2 = 0; j2 < NJ2; j2++) t2[t][j2] = 0ull;
        }

        #pragma unroll
        for (int c = 0; c < HC; c++) {
            const int i0 = c * 64 + lane * 2;
            float2 xv0 = *reinterpret_cast<const float2*>(xr0 + i0);
            float2 xv1 = *reinterpret_cast<const float2*>(xr1 + i0);
            float2 xv2 = *reinterpret_cast<const float2*>(xr2 + i0);
            float2 xv3 = *reinterpret_cast<const float2*>(xr3 + i0);

            s0[0] += xv0.x + xv0.y;  s1[0] += xv0.x * xv0.x + xv0.y * xv0.y;
            s0[1] += xv1.x + xv1.y;  s1[1] += xv1.x * xv1.x + xv1.y * xv1.y;
            s0[2] += xv2.x + xv2.y;  s1[2] += xv2.x * xv2.x + xv2.y * xv2.y;
            s0[3] += xv3.x + xv3.y;  s1[3] += xv3.x * xv3.x + xv3.y * xv3.y;

            ull xp[TTOK][2];
            xp[0][0] = packbb(xv0.x); xp[0][1] = packbb(xv0.y);
            xp[1][0] = packbb(xv1.x); xp[1][1] = packbb(xv1.y);
            xp[2][0] = packbb(xv2.x); xp[2][1] = packbb(xv2.y);
            xp[3][0] = packbb(xv3.x); xp[3][1] = packbb(xv3.y);

            #pragma unroll
            for (int j2 = 0; j2 < NJ2; j2++) {
                ulonglong2 w = *reinterpret_cast<const ulonglong2*>(sW2d + j2 * HDIM + i0);
                #pragma unroll
                for (int t = 0; t < TTOK; t++) {
                    t2[t][j2] = ffma2(xp[t][0], w.x, t2[t][j2]);
                    t2[t][j2] = ffma2(xp[t][1], w.y, t2[t][j2]);
                }
            }
        }

        // ---- fold reduction: token t -> 8-lane group t
        ull E[NJ2 + 1];
        #pragma unroll
        for (int v = 0; v < NJ2 + 1; v++) {
            ull v0 = (v == 0) ? pack2(s0[0], s1[0]) : t2[0][v - 1];
            ull v1 = (v == 0) ? pack2(s0[1], s1[1]) : t2[1][v - 1];
            ull v2 = (v == 0) ? pack2(s0[2], s1[2]) : t2[2][v - 1];
            ull v3 = (v == 0) ? pack2(s0[3], s1[3]) : t2[3][v - 1];
            ull w0 = add2(v0, shfl64(v0, 16));
            ull w1 = add2(v1, shfl64(v1, 16));
            ull w2 = add2(v2, shfl64(v2, 16));
            ull w3 = add2(v3, shfl64(v3, 16));
            ull ea = sg ? w2 : w0;
            ull eb = sg ? w3 : w1;
            ull ya = add2(ea, shfl64(ea, 8));
            ull yb = add2(eb, shfl64(eb, 8));
            ull e = qb ? yb : ya;
            e = add2(e, shfl64(e, 4));
            e = add2(e, shfl64(e, 2));
            e = add2(e, shfl64(e, 1));
            E[v] = e;
        }

        // ---- middle (per 8-lane segment; 4 tokens in parallel)
        float s0v, s1v;
        unpack2(E[0], s0v, s1v);
        float mean = s0v * (1.f / HDIM);
        float var  = s1v * (1.f / HDIM) - mean * mean;
        float rstd = rsqrtf(var + 1e-12f);

        float dv[DDIM];
        float dsum = 0.f;
        #pragma unroll
        for (int j2 = 0; j2 < NJ2; j2++) {
            float tl, th;
            unpack2(E[1 + j2], tl, th);
            float a = rstd * (tl - mean * sC1[2 * j2])     + sC2[2 * j2];
            float b = rstd * (th - mean * sC1[2 * j2 + 1]) + sC2[2 * j2 + 1];
            dv[2 * j2] = a; dv[2 * j2 + 1] = b;
            dsum += a + b;
        }
        float dmean = dsum * (1.f / DDIM);
        float dvar = 0.f;
        #pragma unroll
        for (int j = 0; j < DDIM; j++) { float df = dv[j] - dmean; dvar += df * df; }
        float drs = rsqrtf(dvar * (1.f / DDIM) + 1e-12f);

        ull qp[NJ2];
        #pragma unroll
        for (int j2 = 0; j2 < NJ2; j2++) {
            float qa = (dv[2 * j2]     - dmean) * drs * sG2[2 * j2]     + sB2[2 * j2];
            float qc = (dv[2 * j2 + 1] - dmean) * drs * sG2[2 * j2 + 1] + sB2[2 * j2 + 1];
            qp[j2] = pack2(qa, qc);
        }

        // attention: lane sl7 owns slots sl7+8k, k=0..6 (padded to 56)
        float sc[7];
        #pragma unroll
        for (int k = 0; k < 7; k++) {
            const ull* kr = sKey2 + (sl7 + 8 * k) * KP;
            ull acc = 0ull;
            #pragma unroll
            for (int j2 = 0; j2 < NJ2; j2++) acc = ffma2(qp[j2], kr[j2], acc);
            float l, h;
            unpack2(acc, l, h);
            sc[k] = l + h;
        }
        float mx = sc[0];
        #pragma unroll
        for (int k = 1; k < 7; k++) mx = fmaxf(mx, sc[k]);
        #pragma unroll
        for (int off = 4; off > 0; off >>= 1)
            mx = fmaxf(mx, __shfl_xor_sync(0xffffffffu, mx, off));

        float ex[7];
        #pragma unroll
        for (int k = 0; k < 6; k++) ex[k] = __expf(sc[k] - mx);
        ex[6] = (sl7 < 2) ? __expf(sc[6] - mx) : 0.f;

        // NOTE: softmax 1/sum and exp(-mx) are uniform scales -> cancel in LN3.
        ull mo[NJ2];
        #pragma unroll
        for (int j2 = 0; j2 < NJ2; j2++) mo[j2] = 0ull;
        #pragma unroll
        for (int k = 0; k < 7; k++) {
            const ull* vr = sVal2 + (sl7 + 8 * k) * KP;
            ull pb = packbb(ex[k]);
            #pragma unroll
            for (int j2 = 0; j2 < NJ2; j2++) mo[j2] = ffma2(pb, vr[j2], mo[j2]);
        }
        #pragma unroll
        for (int off = 4; off > 0; off >>= 1) {
            #pragma unroll
            for (int j2 = 0; j2 < NJ2; j2++)
                mo[j2] = add2(mo[j2], shfl64(mo[j2], off));
        }

        // LN3 on unnormalized mo
        float msum = 0.f;
        #pragma unroll
        for (int j2 = 0; j2 < NJ2; j2++) {
            float l, h;
            unpack2(mo[j2], l, h);
            msum += l + h;
        }
        float mmean = msum * (1.f / DDIM);
        float mvar = 0.f;
        #pragma unroll
        for (int j2 = 0; j2 < NJ2; j2++) {
            float l, h;
            unpack2(mo[j2], l, h);
            float fl = l - mmean, fh = h - mmean;
            mvar += fl * fl + fh * fh;
        }
        float mrs = rsqrtf(mvar * (1.f / DDIM) + 1e-12f);

        ull qo[NJ2];
        #pragma unroll
        for (int j2 = 0; j2 < NJ2; j2++) {
            float l, h;
            unpack2(mo[j2], l, h);
            float oa = (l - mmean) * mrs * sG3[2 * j2]     + sB3[2 * j2];
            float ob = (h - mmean) * mrs * sG3[2 * j2 + 1] + sB3[2 * j2 + 1];
            qo[j2] = pack2(oa, ob);
        }

        // ---- store packed memn: lanes sl7=0..3 of each segment store 16B each
        const int tok = tok0 + tt;
        ull lo, hi;
        if (sl7 == 0)      { lo = qo[0]; hi = qo[1]; }
        else if (sl7 == 1) { lo = qo[2]; hi = qo[3]; }
        else if (sl7 == 2) { lo = qo[4]; hi = qo[5]; }
        else               { lo = qo[6]; hi = qo[7]; }
        if (sl7 < 4 && tok < ntok) {
            *reinterpret_cast<ulonglong2*>(g_memn + (size_t)tok * NJ2 + 2 * sl7) =
                make_ulonglong2(lo, hi);
        }
    }
}

// =====================================================================
// Kernel B: out = memn @ W_up + b_up  — register-resident weights.
// Block = 192 threads (6 warps); warp w owns cols [w*128, w*128+128),
// lane owns 4 consecutive columns. Tile of 128 tokens staged in smem.
// =====================================================================
__global__ __launch_bounds__(192, 3) void up_kernel(
    const float* __restrict__ Wup, const float* __restrict__ bup,
    float* __restrict__ out, int ntok)
{
    __shared__ ull sQ[TB * NJ2];    // 8 KB

    const int tid = threadIdx.x;
    const int warp = tid >> 5;
    const int lane = tid & 31;
    const int i0 = warp * 128 + lane * 4;

    // register weights: wc{0..3}[j2] = pack2(Wup[2j2][i0+c], Wup[2j2+1][i0+c])
    ull wc0[NJ2], wc1[NJ2], wc2[NJ2], wc3[NJ2];
    #pragma unroll
    for (int j2 = 0; j2 < NJ2; j2++) {
        float4 r0 = *reinterpret_cast<const float4*>(Wup + (2 * j2) * HDIM + i0);
        float4 r1 = *reinterpret_cast<const float4*>(Wup + (2 * j2 + 1) * HDIM + i0);
        wc0[j2] = pack2(r0.x, r1.x);
        wc1[j2] = pack2(r0.y, r1.y);
        wc2[j2] = pack2(r0.z, r1.z);
        wc3[j2] = pack2(r0.w, r1.w);
    }
    const float4 bias = *reinterpret_cast<const float4*>(bup + i0);

    for (int tb = blockIdx.x * TB; tb < ntok; tb += gridDim.x * TB) {
        __syncthreads();   // protect sQ reuse across iterations
        for (int i = tid; i < TB * NJ2; i += 192) {
            int t = i >> 3;
            if (tb + t < ntok) sQ[i] = g_memn[(size_t)(tb + t) * NJ2 + (i & 7)];
        }
        __syncthreads();

        int tmax = ntok - tb;
        if (tmax > TB) tmax = TB;
        for (int t = 0; t < tmax; t++) {
            const ull* q = sQ + t * NJ2;
            ulonglong2 q01 = *reinterpret_cast<const ulonglong2*>(q);
            ulonglong2 q23 = *reinterpret_cast<const ulonglong2*>(q + 2);
            ulonglong2 q45 = *reinterpret_cast<const ulonglong2*>(q + 4);
            ulonglong2 q67 = *reinterpret_cast<const ulonglong2*>(q + 6);
            ull a0 = 0ull, a1 = 0ull, a2 = 0ull, a3 = 0ull;

            a0 = ffma2(q01.x, wc0[0], a0); a1 = ffma2(q01.x, wc1[0], a1);
            a2 = ffma2(q01.x, wc2[0], a2); a3 = ffma2(q01.x, wc3[0], a3);
            a0 = ffma2(q01.y, wc0[1], a0); a1 = ffma2(q01.y, wc1[1], a1);
            a2 = ffma2(q01.y, wc2[1], a2); a3 = ffma2(q01.y, wc3[1], a3);
            a0 = ffma2(q23.x, wc0[2], a0); a1 = ffma2(q23.x, wc1[2], a1);
            a2 = ffma2(q23.x, wc2[2], a2); a3 = ffma2(q23.x, wc3[2], a3);
            a0 = ffma2(q23.y, wc0[3], a0); a1 = ffma2(q23.y, wc1[3], a1);
            a2 = ffma2(q23.y, wc2[3], a2); a3 = ffma2(q23.y, wc3[3], a3);
            a0 = ffma2(q45.x, wc0[4], a0); a1 = ffma2(q45.x, wc1[4], a1);
            a2 = ffma2(q45.x, wc2[4], a2); a3 = ffma2(q45.x, wc3[4], a3);
            a0 = ffma2(q45.y, wc0[5], a0); a1 = ffma2(q45.y, wc1[5], a1);
            a2 = ffma2(q45.y, wc2[5], a2); a3 = ffma2(q45.y, wc3[5], a3);
            a0 = ffma2(q67.x, wc0[6], a0); a1 = ffma2(q67.x, wc1[6], a1);
            a2 = ffma2(q67.x, wc2[6], a2); a3 = ffma2(q67.x, wc3[6], a3);
            a0 = ffma2(q67.y, wc0[7], a0); a1 = ffma2(q67.y, wc1[7], a1);
            a2 = ffma2(q67.y, wc2[7], a2); a3 = ffma2(q67.y, wc3[7], a3);

            float l, h;
            float4 o;
            unpack2(a0, l, h); o.x = l + h + bias.x;
            unpack2(a1, l, h); o.y = l + h + bias.y;
            unpack2(a2, l, h); o.z = l + h + bias.z;
            unpack2(a3, l, h); o.w = l + h + bias.w;
            *reinterpret_cast<float4*>(out + (size_t)(tb + t) * HDIM + i0) = o;
        }
    }
}

extern "C" void kernel_launch(void* const* d_in, const int* in_sizes, int n_in,
                              void* d_out, int out_size)
{
    const float* x   = (const float*)d_in[0];
    const float* g1  = (const float*)d_in[1];
    const float* b1  = (const float*)d_in[2];
    const float* Wd  = (const float*)d_in[3];
    const float* bd  = (const float*)d_in[4];
    const float* g2  = (const float*)d_in[5];
    const float* b2  = (const float*)d_in[6];
    const float* mem = (const float*)d_in[7];
    const float* Wk  = (const float*)d_in[8];
    const float* bk  = (const float*)d_in[9];
    const float* Wv  = (const float*)d_in[10];
    const float* bv  = (const float*)d_in[11];
    const float* g3  = (const float*)d_in[12];
    const float* b3  = (const float*)d_in[13];
    const float* Wup = (const float*)d_in[14];
    const float* bup = (const float*)d_in[15];
    float* out = (float*)d_out;

    int ntok = in_sizes[0] / HDIM;
    if (ntok > 65536) ntok = 65536;

    precompute_kernel<<<148, 256>>>(g1, b1, Wd, bd, mem, Wk, bk, Wv, bv);

    size_t smA = (size_t)(NJ2 * HDIM + 2 * MPAD * KP) * sizeof(ull)
               + (size_t)(6 * DDIM) * sizeof(float);
    cudaFuncSetAttribute(down_kernel, cudaFuncAttributeMaxDynamicSharedMemorySize, (int)smA);
    down_kernel<<<NBLK, 256, smA>>>(x, g2, b2, g3, b3, ntok);

    int nblkB = (ntok + TB - 1) / TB;
    up_kernel<<<nblkB, 192>>>(Wup, bup, out, ntok);
}

// round 8
// speedup vs baseline: 3.3307x; 1.0004x over previous
#include <cuda_runtime.h>

#define HDIM 768
#define DDIM 16
#define MDIM 50
#define MPAD 56           // padded slot count, 7 per lane of an 8-lane segment
#define KP   9            // key/val row pitch in ull (conflict-free)
#define NJ2  8            // DDIM/2 packed pairs
#define HC   12           // 768 / (32 lanes * 2 cols)
#define TTOK 4
#define NBLK 296
#define NWRP 8

typedef unsigned long long ull;

// ---------- packed f32x2 helpers ----------
__device__ __forceinline__ ull ffma2(ull a, ull b, ull c) {
    ull d;
    asm("fma.rn.f32x2 %0, %1, %2, %3;" : "=l"(d) : "l"(a), "l"(b), "l"(c));
    return d;
}
__device__ __forceinline__ ull add2(ull a, ull b) {
    ull d;
    asm("add.rn.f32x2 %0, %1, %2;" : "=l"(d) : "l"(a), "l"(b));
    return d;
}
__device__ __forceinline__ ull pack2(float lo, float hi) {
    ull r;
    asm("mov.b64 %0, {%1, %2};" : "=l"(r) : "f"(lo), "f"(hi));
    return r;
}
__device__ __forceinline__ ull packbb(float v) {
    ull r;
    asm("mov.b64 %0, {%1, %1};" : "=l"(r) : "f"(v));
    return r;
}
__device__ __forceinline__ void unpack2(ull v, float& lo, float& hi) {
    asm("mov.b64 {%0, %1}, %2;" : "=f"(lo), "=f"(hi) : "l"(v));
}
__device__ __forceinline__ ull shfl64(ull v, int off) {
    return __shfl_xor_sync(0xffffffffu, v, off);
}

// LN3 scratch between the two kernels (zero-init device global; allocation-free)
__device__ __align__(16) ull g_memn[(size_t)65536 * NJ2];

// =====================================================================
// Kernel A: per-block weight prep + LN1 + down-proj + LN2 + attention
//           + LN3 -> g_memn (packed). No separate precompute launch.
// =====================================================================
__global__ __launch_bounds__(256, 2) void down_kernel(
    const float* __restrict__ x,
    const float* __restrict__ g1, const float* __restrict__ b1,
    const float* __restrict__ Wd, const float* __restrict__ bd,
    const float* __restrict__ mem,
    const float* __restrict__ Wk, const float* __restrict__ bk,
    const float* __restrict__ Wv, const float* __restrict__ bv,
    const float* __restrict__ g2, const float* __restrict__ b2,
    const float* __restrict__ g3, const float* __restrict__ b3,
    int ntok)
{
    extern __shared__ ull sm[];
    ull* sW2d  = sm;                              // 6144
    ull* sKey2 = sW2d + NJ2 * HDIM;               // 504
    ull* sVal2 = sKey2 + MPAD * KP;               // 504
    float* sC1 = (float*)(sVal2 + MPAD * KP);
    float* sC2 = sC1 + DDIM;
    float* sG2 = sC2 + DDIM;
    float* sB2 = sG2 + DDIM;
    float* sG3 = sB2 + DDIM;
    float* sB3 = sG3 + DDIM;

    const int tid = threadIdx.x;
    const int lane = tid & 31;
    const int warp = tid >> 5;

    // ---------------- per-block weight prep (replaces precompute kernel) ----
    // packed g1-folded down weights: sW2d[j2*HDIM+i] = (g1[i]*Wd[i][2j2], g1[i]*Wd[i][2j2+1])
    for (int id = tid; id < NJ2 * HDIM; id += 256) {
        int j2 = id / HDIM, i = id % HDIM;
        float gi = g1[i];
        sW2d[id] = pack2(gi * Wd[i * DDIM + 2 * j2], gi * Wd[i * DDIM + 2 * j2 + 1]);
    }
    // key/val = mem @ Wk + bk, mem @ Wv + bv  (packed j-pairs, pitch KP)
    for (int id = tid; id < MDIM * NJ2; id += 256) {
        int m = id / NJ2, j2 = id % NJ2;
        float ak0 = bk[2 * j2], ak1 = bk[2 * j2 + 1];
        float av0 = bv[2 * j2], av1 = bv[2 * j2 + 1];
        #pragma unroll
        for (int k = 0; k < DDIM; k++) {
            float mv = mem[m * DDIM + k];
            ak0 += mv * Wk[k * DDIM + 2 * j2];
            ak1 += mv * Wk[k * DDIM + 2 * j2 + 1];
            av0 += mv * Wv[k * DDIM + 2 * j2];
            av1 += mv * Wv[k * DDIM + 2 * j2 + 1];
        }
        sKey2[m * KP + j2] = pack2(ak0, ak1);
        sVal2[m * KP + j2] = pack2(av0, av1);
    }
    // zero the padded slots 50..55 (read by the branch-free attention loop)
    for (int id = tid; id < (MPAD - MDIM) * NJ2; id += 256) {
        int m = MDIM + id / NJ2, j2 = id % NJ2;
        sKey2[m * KP + j2] = 0ull;
        sVal2[m * KP + j2] = 0ull;
    }
    // c1[j] = sum_i g1[i]*Wd[i][j], c2[j] = sum_i b1[i]*Wd[i][j] + bd[j]
    {
        int j0 = warp * 2;
        ull cA = 0ull, cB = 0ull;   // (c1[j0],c2[j0]) , (c1[j0+1],c2[j0+1])
        #pragma unroll
        for (int it = 0; it < HDIM / 32; it++) {
            int i = it * 32 + lane;
            float gi = g1[i], bi = b1[i];
            float w0 = Wd[i * DDIM + j0];
            float w1 = Wd[i * DDIM + j0 + 1];
            cA = add2(cA, pack2(gi * w0, bi * w0));
            cB = add2(cB, pack2(gi * w1, bi * w1));
        }
        #pragma unroll
        for (int off = 16; off > 0; off >>= 1) {
            cA = add2(cA, shfl64(cA, off));
            cB = add2(cB, shfl64(cB, off));
        }
        if (lane == 0) {
            float c1a, c2a, c1b, c2b;
            unpack2(cA, c1a, c2a);
            unpack2(cB, c1b, c2b);
            sC1[j0] = c1a;     sC2[j0] = c2a + bd[j0];
            sC1[j0 + 1] = c1b; sC2[j0 + 1] = c2b + bd[j0 + 1];
        }
    }
    if (tid < DDIM) {
        sG2[tid] = g2[tid]; sB2[tid] = b2[tid];
        sG3[tid] = g3[tid]; sB3[tid] = b3[tid];
    }
    __syncthreads();

    const int sg = lane >> 4;
    const int qb = (lane >> 3) & 1;
    const int tt = lane >> 3;          // token index within group owned by segment
    const int sl7 = lane & 7;
    const int gw = blockIdx.x * NWRP + warp;
    const int gstride = NBLK * NWRP * TTOK;

    for (int tok0 = gw * TTOK; tok0 < ntok; tok0 += gstride) {
        int row[TTOK];
        #pragma unroll
        for (int t = 0; t < TTOK; t++) {
            int r = tok0 + t;
            row[t] = (r < ntok) ? r : (ntok - 1);
        }
        const float* xr0 = x + (size_t)row[0] * HDIM;
        const float* xr1 = x + (size_t)row[1] * HDIM;
        const float* xr2 = x + (size_t)row[2] * HDIM;
        const float* xr3 = x + (size_t)row[3] * HDIM;

        // ---- pass 1: LN1 stats + packed down-projection
        ull t2[TTOK][NJ2];
        float s0[TTOK], s1[TTOK];
        #pragma unroll
        for (int t = 0; t < TTOK; t++) {
            s0[t] = 0.f; s1[t] = 0.f;
            #pragma unroll
            for (int j2 = 0; j2 < NJ2; j2++) t2[t][j2] = 0ull;
        }

        #pragma unroll
        for (int c = 0; c < HC; c++) {
            const int i0 = c * 64 + lane * 2;
            float2 xv0 = *reinterpret_cast<const float2*>(xr0 + i0);
            float2 xv1 = *reinterpret_cast<const float2*>(xr1 + i0);
            float2 xv2 = *reinterpret_cast<const float2*>(xr2 + i0);
            float2 xv3 = *reinterpret_cast<const float2*>(xr3 + i0);

            s0[0] += xv0.x + xv0.y;  s1[0] += xv0.x * xv0.x + xv0.y * xv0.y;
            s0[1] += xv1.x + xv1.y;  s1[1] += xv1.x * xv1.x + xv1.y * xv1.y;
            s0[2] += xv2.x + xv2.y;  s1[2] += xv2.x * xv2.x + xv2.y * xv2.y;
            s0[3] += xv3.x + xv3.y;  s1[3] += xv3.x * xv3.x + xv3.y * xv3.y;

            ull xp[TTOK][2];
            xp[0][0] = packbb(xv0.x); xp[0][1] = packbb(xv0.y);
            xp[1][0] = packbb(xv1.x); xp[1][1] = packbb(xv1.y);
            xp[2][0] = packbb(xv2.x); xp[2][1] = packbb(xv2.y);
            xp[3][0] = packbb(xv3.x); xp[3][1] = packbb(xv3.y);

            #pragma unroll
            for (int j2 = 0; j2 < NJ2; j2++) {
                ulonglong2 w = *reinterpret_cast<const ulonglong2*>(sW2d + j2 * HDIM + i0);
                #pragma unroll
                for (int t = 0; t < TTOK; t++) {
                    t2[t][j2] = ffma2(xp[t][0], w.x, t2[t][j2]);
                    t2[t][j2] = ffma2(xp[t][1], w.y, t2[t][j2]);
                }
            }
        }

        // ---- fold reduction: token t -> 8-lane group t
        ull E[NJ2 + 1];
        #pragma unroll
        for (int v = 0; v < NJ2 + 1; v++) {
            ull v0 = (v == 0) ? pack2(s0[0], s1[0]) : t2[0][v - 1];
            ull v1 = (v == 0) ? pack2(s0[1], s1[1]) : t2[1][v - 1];
            ull v2 = (v == 0) ? pack2(s0[2], s1[2]) : t2[2][v - 1];
            ull v3 = (v == 0) ? pack2(s0[3], s1[3]) : t2[3][v - 1];
            ull w0 = add2(v0, shfl64(v0, 16));
            ull w1 = add2(v1, shfl64(v1, 16));
            ull w2 = add2(v2, shfl64(v2, 16));
            ull w3 = add2(v3, shfl64(v3, 16));
            ull ea = sg ? w2 : w0;
            ull eb = sg ? w3 : w1;
            ull ya = add2(ea, shfl64(ea, 8));
            ull yb = add2(eb, shfl64(eb, 8));
            ull e = qb ? yb : ya;
            e = add2(e, shfl64(e, 4));
            e = add2(e, shfl64(e, 2));
            e = add2(e, shfl64(e, 1));
            E[v] = e;
        }

        // ---- middle (per 8-lane segment; 4 tokens in parallel)
        float s0v, s1v;
        unpack2(E[0], s0v, s1v);
        float mean = s0v * (1.f / HDIM);
        float var  = s1v * (1.f / HDIM) - mean * mean;
        float rstd = rsqrtf(var + 1e-12f);

        float dv[DDIM];
        float dsum = 0.f;
        #pragma unroll
        for (int j2 = 0; j2 < NJ2; j2++) {
            float tl, th;
            unpack2(E[1 + j2], tl, th);
            float a = rstd * (tl - mean * sC1[2 * j2])     + sC2[2 * j2];
            float b = rstd * (th - mean * sC1[2 * j2 + 1]) + sC2[2 * j2 + 1];
            dv[2 * j2] = a; dv[2 * j2 + 1] = b;
            dsum += a + b;
        }
        float dmean = dsum * (1.f / DDIM);
        float dvar = 0.f;
        #pragma unroll
        for (int j = 0; j < DDIM; j++) { float df = dv[j] - dmean; dvar += df * df; }
        float drs = rsqrtf(dvar * (1.f / DDIM) + 1e-12f);

        ull qp[NJ2];
        #pragma unroll
        for (int j2 = 0; j2 < NJ2; j2++) {
            float qa = (dv[2 * j2]     - dmean) * drs * sG2[2 * j2]     + sB2[2 * j2];
            float qc = (dv[2 * j2 + 1] - dmean) * drs * sG2[2 * j2 + 1] + sB2[2 * j2 + 1];
            qp[j2] = pack2(qa, qc);
        }

        // attention: lane sl7 owns slots sl7+8k, k=0..6 (padded to 56).
        // exp(sc) without max-shift: e^{-mx} and 1/sum are uniform scales
        // that cancel exactly in LN3 (scores here are O(1e-2)).
        float ex[7];
        #pragma unroll
        for (int k = 0; k < 7; k++) {
            const ull* kr = sKey2 + (sl7 + 8 * k) * KP;
            ull acc = 0ull;
            #pragma unroll
            for (int j2 = 0; j2 < NJ2; j2++) acc = ffma2(qp[j2], kr[j2], acc);
            float l, h;
            unpack2(acc, l, h);
            float sc = l + h;
            ex[k] = __expf(sc);
        }
        if (sl7 >= 2) ex[6] = 0.f;     // slots 50..55 are padding

        ull mo[NJ2];
        #pragma unroll
        for (int j2 = 0; j2 < NJ2; j2++) mo[j2] = 0ull;
        #pragma unroll
        for (int k = 0; k < 7; k++) {
            const ull* vr = sVal2 + (sl7 + 8 * k) * KP;
            ull pb = packbb(ex[k]);
            #pragma unroll
            for (int j2 = 0; j2 < NJ2; j2++) mo[j2] = ffma2(pb, vr[j2], mo[j2]);
        }
        #pragma unroll
        for (int off = 4; off > 0; off >>= 1) {
            #pragma unroll
            for (int j2 = 0; j2 < NJ2; j2++)
                mo[j2] = add2(mo[j2], shfl64(mo[j2], off));
        }

        // LN3 on unnormalized mo
        float msum = 0.f;
        #pragma unroll
        for (int j2 = 0; j2 < NJ2; j2++) {
            float l, h;
            unpack2(mo[j2], l, h);
            msum += l + h;
        }
        float mmean = msum * (1.f / DDIM);
        float mvar = 0.f;
        #pragma unroll
        for (int j2 = 0; j2 < NJ2; j2++) {
            float l, h;
            unpack2(mo[j2], l, h);
            float fl = l - mmean, fh = h - mmean;
            mvar += fl * fl + fh * fh;
        }
        float mrs = rsqrtf(mvar * (1.f / DDIM) + 1e-12f);

        ull qo[NJ2];
        #pragma unroll
        for (int j2 = 0; j2 < NJ2; j2++) {
            float l, h;
            unpack2(mo[j2], l, h);
            float oa = (l - mmean) * mrs * sG3[2 * j2]     + sB3[2 * j2];
            float ob = (h - mmean) * mrs * sG3[2 * j2 + 1] + sB3[2 * j2 + 1];
            qo[j2] = pack2(oa, ob);
        }

        // ---- store packed memn: lanes sl7=0..3 of each segment store 16B each
        const int tok = tok0 + tt;
        ull lo, hi;
        if (sl7 == 0)      { lo = qo[0]; hi = qo[1]; }
        else if (sl7 == 1) { lo = qo[2]; hi = qo[3]; }
        else if (sl7 == 2) { lo = qo[4]; hi = qo[5]; }
        else               { lo = qo[6]; hi = qo[7]; }
        if (sl7 < 4 && tok < ntok) {
            *reinterpret_cast<ulonglong2*>(g_memn + (size_t)tok * NJ2 + 2 * sl7) =
                make_ulonglong2(lo, hi);
        }
    }
}

// =====================================================================
// Kernel B: out = memn @ W_up + b_up  — register-resident weights.
// Block = 192 threads; warp w owns cols [w*128, w*128+128), lane owns 4.
// One balanced tile of <=tb tokens per block (grid = ceil(ntok/tb)).
// =====================================================================
__global__ __launch_bounds__(192, 3) void up_kernel(
    const float* __restrict__ Wup, const float* __restrict__ bup,
    float* __restrict__ out, int ntok, int tb)
{
    __shared__ ull sQ[128 * NJ2];    // 8 KB

    const int tid = threadIdx.x;
    const int warp = tid >> 5;
    const int lane = tid & 31;
    const int i0 = warp * 128 + lane * 4;

    ull wc0[NJ2], wc1[NJ2], wc2[NJ2], wc3[NJ2];
    #pragma unroll
    for (int j2 = 0; j2 < NJ2; j2++) {
        float4 r0 = *reinterpret_cast<const float4*>(Wup + (2 * j2) * HDIM + i0);
        float4 r1 = *reinterpret_cast<const float4*>(Wup + (2 * j2 + 1) * HDIM + i0);
        wc0[j2] = pack2(r0.x, r1.x);
        wc1[j2] = pack2(r0.y, r1.y);
        wc2[j2] = pack2(r0.z, r1.z);
        wc3[j2] = pack2(r0.w, r1.w);
    }
    const float4 bias = *reinterpret_cast<const float4*>(bup + i0);

    const int tb0 = blockIdx.x * tb;
    int tmax = ntok - tb0;
    if (tmax > tb) tmax = tb;
    if (tmax <= 0) return;

    for (int i = tid; i < tmax * NJ2; i += 192)
        sQ[i] = g_memn[(size_t)tb0 * NJ2 + i];
    __syncthreads();

    #pragma unroll 2
    for (int t = 0; t < tmax; t++) {
        const ull* q = sQ + t * NJ2;
        ulonglong2 q01 = *reinterpret_cast<const ulonglong2*>(q);
        ulonglong2 q23 = *reinterpret_cast<const ulonglong2*>(q + 2);
        ulonglong2 q45 = *reinterpret_cast<const ulonglong2*>(q + 4);
        ulonglong2 q67 = *reinterpret_cast<const ulonglong2*>(q + 6);
        ull a0 = 0ull, a1 = 0ull, a2 = 0ull, a3 = 0ull;

        a0 = ffma2(q01.x, wc0[0], a0); a1 = ffma2(q01.x, wc1[0], a1);
        a2 = ffma2(q01.x, wc2[0], a2); a3 = ffma2(q01.x, wc3[0], a3);
        a0 = ffma2(q01.y, wc0[1], a0); a1 = ffma2(q01.y, wc1[1], a1);
        a2 = ffma2(q01.y, wc2[1], a2); a3 = ffma2(q01.y, wc3[1], a3);
        a0 = ffma2(q23.x, wc0[2], a0); a1 = ffma2(q23.x, wc1[2], a1);
        a2 = ffma2(q23.x, wc2[2], a2); a3 = ffma2(q23.x, wc3[2], a3);
        a0 = ffma2(q23.y, wc0[3], a0); a1 = ffma2(q23.y, wc1[3], a1);
        a2 = ffma2(q23.y, wc2[3], a2); a3 = ffma2(q23.y, wc3[3], a3);
        a0 = ffma2(q45.x, wc0[4], a0); a1 = ffma2(q45.x, wc1[4], a1);
        a2 = ffma2(q45.x, wc2[4], a2); a3 = ffma2(q45.x, wc3[4], a3);
        a0 = ffma2(q45.y, wc0[5], a0); a1 = ffma2(q45.y, wc1[5], a1);
        a2 = ffma2(q45.y, wc2[5], a2); a3 = ffma2(q45.y, wc3[5], a3);
        a0 = ffma2(q67.x, wc0[6], a0); a1 = ffma2(q67.x, wc1[6], a1);
        a2 = ffma2(q67.x, wc2[6], a2); a3 = ffma2(q67.x, wc3[6], a3);
        a0 = ffma2(q67.y, wc0[7], a0); a1 = ffma2(q67.y, wc1[7], a1);
        a2 = ffma2(q67.y, wc2[7], a2); a3 = ffma2(q67.y, wc3[7], a3);

        float l, h;
        float4 o;
        unpack2(a0, l, h); o.x = l + h + bias.x;
        unpack2(a1, l, h); o.y = l + h + bias.y;
        unpack2(a2, l, h); o.z = l + h + bias.z;
        unpack2(a3, l, h); o.w = l + h + bias.w;
        *reinterpret_cast<float4*>(out + (size_t)(tb0 + t) * HDIM + i0) = o;
    }
}

extern "C" void kernel_launch(void* const* d_in, const int* in_sizes, int n_in,
                              void* d_out, int out_size)
{
    const float* x   = (const float*)d_in[0];
    const float* g1  = (const float*)d_in[1];
    const float* b1  = (const float*)d_in[2];
    const float* Wd  = (const float*)d_in[3];
    const float* bd  = (const float*)d_in[4];
    const float* g2  = (const float*)d_in[5];
    const float* b2  = (const float*)d_in[6];
    const float* mem = (const float*)d_in[7];
    const float* Wk  = (const float*)d_in[8];
    const float* bk  = (const float*)d_in[9];
    const float* Wv  = (const float*)d_in[10];
    const float* bv  = (const float*)d_in[11];
    const float* g3  = (const float*)d_in[12];
    const float* b3  = (const float*)d_in[13];
    const float* Wup = (const float*)d_in[14];
    const float* bup = (const float*)d_in[15];
    float* out = (float*)d_out;

    int ntok = in_sizes[0] / HDIM;
    if (ntok > 65536) ntok = 65536;

    size_t smA = (size_t)(NJ2 * HDIM + 2 * MPAD * KP) * sizeof(ull)
               + (size_t)(6 * DDIM) * sizeof(float);
    cudaFuncSetAttribute(down_kernel, cudaFuncAttributeMaxDynamicSharedMemorySize, (int)smA);
    down_kernel<<<NBLK, 256, smA>>>(x, g1, b1, Wd, bd, mem, Wk, bk, Wv, bv,
                                    g2, b2, g3, b3, ntok);

    int tb = (ntok + NBLK - 1) / NBLK;     // balanced: one tile per block, 2 blocks/SM
    if (tb > 128) tb = 128;
    int gridB = (ntok + tb - 1) / tb;
    up_kernel<<<gridB, 192>>>(Wup, bup, out, ntok, tb);
}